// round 1
// baseline (speedup 1.0000x reference)
#include <cuda_runtime.h>

#define B_ 4
#define N_ 2048
#define V_ 12
#define C_ 50
#define P_ 16384   /* H*W = 128*128 */

// Scratch (no allocations allowed): winner keys + per-pixel softmax stats.
__device__ int   g_winner[B_ * V_ * N_];          // 393 KB
__device__ float g_mx[B_ * V_ * P_];              // 3.1 MB (only mask-passing pixels used)
__device__ float g_se[B_ * V_ * P_];              // 3.1 MB

__global__ void init_winner_kernel() {
    int i = blockIdx.x * blockDim.x + threadIdx.x;
    if (i < B_ * V_ * N_) g_winner[i] = -1;
}

// One thread per pixel: coalesced read of 50 logits (stride P), argmax in
// registers; only pixels that can win (valid && 1<=argmax<=parts_nb) pay for
// exp + stats store + atomicMax scatter.
__global__ __launch_bounds__(256) void argmax_scatter_kernel(
    const float* __restrict__ pred,        // (B,V,C,P)
    const int*   __restrict__ p2p,         // (B,V,P)
    const int*   __restrict__ parts_nb)    // (B,)
{
    int t = blockIdx.x * blockDim.x + threadIdx.x;
    if (t >= B_ * V_ * P_) return;
    int bv = t / P_;
    int p  = t - bv * P_;
    int b  = bv / V_;

    int point = p2p[t];
    if (point < 0) return;                 // invalid pixel

    const float* base = pred + (size_t)bv * C_ * P_ + p;
    float x[C_];
    float mx = -3.402823466e+38f;
    int   am = 0;
#pragma unroll
    for (int c = 0; c < C_; c++) {
        x[c] = base[(size_t)c * P_];
        if (x[c] > mx) { mx = x[c]; am = c; }   // '>' keeps first occurrence (jnp.argmax)
    }

    int pn = parts_nb[b];
    if (am >= 1 && am <= pn) {
        float se = 0.f;
#pragma unroll
        for (int c = 0; c < C_; c++) se += expf(x[c] - mx);
        g_mx[t] = mx;
        g_se[t] = se;
        int key = am * P_ + p;                   // max over (class, pixel) lexicographic
        atomicMax(&g_winner[bv * N_ + (point & (N_ - 1))], key);
    }
}

// One block per (b, n). Threads 0..V-1 stage winner metadata; threads 0..C-1
// gather the 50 logits at each winning pixel and accumulate weighted probs.
__global__ __launch_bounds__(64) void lift_gather_kernel(
    const float* __restrict__ pred,        // (B,V,C,P)
    const float* __restrict__ vw,          // (B,V)
    float*       __restrict__ out)         // (B,C,N)
{
    int bn = blockIdx.x;
    int b  = bn / N_;
    int n  = bn - b * N_;
    int tid = threadIdx.x;

    __shared__ int   s_pix[V_];
    __shared__ float s_mx[V_];
    __shared__ float s_wse[V_];   // views_weight / sumexp (0 if no winner)
    __shared__ int   s_cnt;

    if (tid == 0) s_cnt = 0;
    __syncthreads();

    if (tid < V_) {
        int key = g_winner[(b * V_ + tid) * N_ + n];
        if (key >= 0) {
            int pix = key & (P_ - 1);
            int bvp = (b * V_ + tid) * P_ + pix;
            s_pix[tid] = pix;
            s_mx[tid]  = g_mx[bvp];
            s_wse[tid] = vw[b * V_ + tid] / g_se[bvp];
            atomicAdd(&s_cnt, 1);
        } else {
            s_pix[tid] = -1;
            s_mx[tid]  = 0.f;
            s_wse[tid] = 0.f;
        }
    }
    __syncthreads();

    if (tid >= C_) return;

    float acc = 0.f;
    const float* pb = pred + ((size_t)b * V_ * C_ + tid) * P_;
#pragma unroll
    for (int v = 0; v < V_; v++) {
        int pix = s_pix[v];
        if (pix >= 0) {
            float x = pb[(size_t)v * C_ * P_ + pix];
            acc += s_wse[v] * expf(x - s_mx[v]);
        }
    }
    float denom = fmaxf((float)s_cnt, 1.f);
    out[((size_t)b * C_ + tid) * N_ + n] = acc / denom;
}

extern "C" void kernel_launch(void* const* d_in, const int* in_sizes, int n_in,
                              void* d_out, int out_size) {
    // inputs: 0 points (unused), 1 predictions_2d, 2 rendered_pix_to_point,
    //         3 views_weights, 4 parts_nb
    const float* pred     = (const float*)d_in[1];
    const int*   p2p      = (const int*)  d_in[2];
    const float* vw       = (const float*)d_in[3];
    const int*   parts_nb = (const int*)  d_in[4];
    float*       out      = (float*)d_out;

    init_winner_kernel<<<(B_ * V_ * N_ + 255) / 256, 256>>>();
    argmax_scatter_kernel<<<(B_ * V_ * P_ + 255) / 256, 256>>>(pred, p2p, parts_nb);
    lift_gather_kernel<<<B_ * N_, 64>>>(pred, vw, out);
}